// round 9
// baseline (speedup 1.0000x reference)
#include <cuda_runtime.h>
#include <cstdint>

#define NNODES 100000
#define NEDGES 640000
#define HID    128

// ---------------- scratch (device globals) ----------------------------------
__device__ float g_Q[(size_t)NNODES * HID];
__device__ float g_K[(size_t)NNODES * HID];
__device__ float g_V[(size_t)NNODES * HID];
__device__ float g_AGG[(size_t)NNODES * HID];
__device__ int   g_deg[NNODES];
__device__ int   g_rowptr[NNODES];
__device__ int   g_cursor[NNODES];
__device__ int   g_perm[NEDGES];     // destination node ids, CSR-grouped
__device__ int   g_total;

// ---------------- helpers ----------------------------------------------------
__device__ __forceinline__ uint32_t f2tf32(float x) {
    uint32_t r;
    asm("cvt.rna.tf32.f32 %0, %1;" : "=r"(r) : "f"(x));
    return r;
}

__device__ __forceinline__ void mma_tf32(float& c0, float& c1, float& c2, float& c3,
                                         uint32_t a0, uint32_t a1, uint32_t a2, uint32_t a3,
                                         uint32_t b0, uint32_t b1) {
    asm volatile(
        "mma.sync.aligned.m16n8k8.row.col.f32.tf32.tf32.f32 "
        "{%0,%1,%2,%3}, {%4,%5,%6,%7}, {%8,%9}, {%0,%1,%2,%3};"
        : "+f"(c0), "+f"(c1), "+f"(c2), "+f"(c3)
        : "r"(a0), "r"(a1), "r"(a2), "r"(a3), "r"(b0), "r"(b1));
}

// ---------------- persistent multi-matrix GEMM (512 threads) -----------------
// Y[M,128] = X[M,128] @ W^T + b for up to 3 (X,W,b,Y) jobs in one kernel.
// W staged tf32(RNA) pair-interleaved so a (k,k+4) B pair is one LDS.64.
// X streams raw fp32 via cp.async.cg double buffer; A-fragments feed the mma
// as RAW fp32 bits (tf32 truncation — no cvt in the critical chain).
#define SLDW 136
#define SXW  132
#define TROWS 128
#define GEMM_SMEM ((128 * SLDW + 2 * TROWS * SXW) * 4)
#define GTH 512

struct Jobs3 {
    const float* X[3];
    const float* W[3];
    const float* b[3];
    float*       Y[3];
    int nmats;
    int M;
};

__device__ __forceinline__ void stage_w(uint32_t* sW, const float* __restrict__ W, int tid) {
    #pragma unroll
    for (int j = 0; j < 8; j++) {
        int f = j * GTH + tid;
        int r = f >> 5, c4 = f & 31, c = c4 * 4;
        float4 w4 = *(const float4*)(W + r * HID + c);
        int base = r * SLDW + (c & ~7) + (c4 & 1);
        sW[base + 0] = f2tf32(w4.x);
        sW[base + 2] = f2tf32(w4.y);
        sW[base + 4] = f2tf32(w4.z);
        sW[base + 6] = f2tf32(w4.w);
    }
}

__device__ __forceinline__ void cp_async_tile(float* sX, const float* __restrict__ X,
                                              int tile, int M, int tid) {
    uint32_t sbase = (uint32_t)__cvta_generic_to_shared(sX);
    int rbase = tile * TROWS;
    #pragma unroll
    for (int j = 0; j < 8; j++) {
        int f = j * GTH + tid;
        int r = f >> 5, c4 = f & 31;
        int gr = rbase + r;
        if (gr < M) {
            uint32_t sa = sbase + (uint32_t)(r * SXW + c4 * 4) * 4u;
            asm volatile("cp.async.cg.shared.global [%0], [%1], 16;"
                         :: "r"(sa), "l"(X + (size_t)gr * HID + c4 * 4));
        }
        // OOB rows: stale smem harmless — those output rows are masked.
    }
}

// A-fragment batch: rows {g, g+8, g+16, g+24}, k in {ko+tig, ko+tig+4}.
__device__ __forceinline__ void lda8(uint32_t a[8], const uint32_t* __restrict__ ax, int ko) {
    a[0] = ax[ko];              a[1] = ax[ko + 4];
    a[2] = ax[ko + 8  * SXW];   a[3] = ax[ko + 8  * SXW + 4];
    a[4] = ax[ko + 16 * SXW];   a[5] = ax[ko + 16 * SXW + 4];
    a[6] = ax[ko + 24 * SXW];   a[7] = ax[ko + 24 * SXW + 4];
}

__device__ __forceinline__ void tile_compute(
    const float* __restrict__ sX, const uint32_t* __restrict__ sW,
    const float* __restrict__ bb,    // 8 per-thread bias values (regs)
    float* __restrict__ Y0,
    int tile, int M, int tid) {

    const int w = tid >> 5, lane = tid & 31;
    const int g = lane >> 2, tig = lane & 3;
    const int mg = w >> 2;              // 4 groups of 32 rows
    const int nbase = (w & 3) * 32;     // 4 column quarters

    float c[2][4][4];
    #pragma unroll
    for (int s = 0; s < 2; s++)
        #pragma unroll
        for (int nt = 0; nt < 4; nt++)
            c[s][nt][0] = c[s][nt][1] = c[s][nt][2] = c[s][nt][3] = 0.f;

    const uint32_t* ax = (const uint32_t*)(sX + (mg * 32 + g) * SXW) + tig;

    uint32_t aC[8], aN[8];
    lda8(aC, ax, 0);

    #pragma unroll
    for (int kt = 0; kt < 16; kt++) {
        const int ko = kt * 8;
        if (kt < 15) lda8(aN, ax, ko + 8);       // pipeline next A batch
        #pragma unroll
        for (int nt = 0; nt < 4; nt++) {
            const uint32_t* bw = sW + (nbase + nt * 8 + g) * SLDW + ko + tig * 2;
            uint2 b = *(const uint2*)bw;
            mma_tf32(c[0][nt][0], c[0][nt][1], c[0][nt][2], c[0][nt][3],
                     aC[0], aC[2], aC[1], aC[3], b.x, b.y);
            mma_tf32(c[1][nt][0], c[1][nt][1], c[1][nt][2], c[1][nt][3],
                     aC[4], aC[6], aC[5], aC[7], b.x, b.y);
        }
        #pragma unroll
        for (int q = 0; q < 8; q++) aC[q] = aN[q];
    }

    #pragma unroll
    for (int s = 0; s < 2; s++) {
        const int row0 = tile * TROWS + mg * 32 + s * 16 + g;
        const int row1 = row0 + 8;
        #pragma unroll
        for (int nt = 0; nt < 4; nt++) {
            int col = nbase + nt * 8 + tig * 2;
            float bb0 = bb[nt * 2], bb1 = bb[nt * 2 + 1];
            if (row0 < M) *(float2*)(Y0 + (size_t)row0 * HID + col) =
                make_float2(c[s][nt][0] + bb0, c[s][nt][1] + bb1);
            if (row1 < M) *(float2*)(Y0 + (size_t)row1 * HID + col) =
                make_float2(c[s][nt][2] + bb0, c[s][nt][3] + bb1);
        }
    }
}

__device__ __forceinline__ void load_bias(float bb[8], const float* __restrict__ b, int tid) {
    const int w = tid >> 5, lane = tid & 31, tig = lane & 3;
    const int nbase = (w & 3) * 32;
    #pragma unroll
    for (int nt = 0; nt < 4; nt++) {
        int col = nbase + nt * 8 + tig * 2;
        bb[nt * 2]     = __ldg(b + col);
        bb[nt * 2 + 1] = __ldg(b + col + 1);
    }
}

extern "C" __global__ void __launch_bounds__(GTH, 1)
gemm_multi(Jobs3 jobs) {
    extern __shared__ uint32_t smem[];
    uint32_t* sW = smem;
    float* sXa = (float*)(smem + 128 * SLDW);
    float* sXb = sXa + TROWS * SXW;

    const int tid = threadIdx.x;
    const int ntiles = (jobs.M + TROWS - 1) / TROWS;
    const int total = ntiles * jobs.nmats;

    int t = blockIdx.x;
    if (t >= total) return;

    int curmat = t / ntiles;
    float bb[8];
    load_bias(bb, jobs.b[curmat], tid);
    stage_w(sW, jobs.W[curmat], tid);
    cp_async_tile(sXa, jobs.X[curmat], t - curmat * ntiles, jobs.M, tid);
    asm volatile("cp.async.commit_group;");

    int p = 0;
    for (; t < total; t += gridDim.x) {
        const int mat = t / ntiles;
        const int tt  = t - mat * ntiles;
        const int tn  = t + gridDim.x;
        float* cur = p ? sXb : sXa;
        float* nxt = p ? sXa : sXb;

        if (tn < total) {
            int matn = tn / ntiles;
            cp_async_tile(nxt, jobs.X[matn], tn - matn * ntiles, jobs.M, tid);
            asm volatile("cp.async.commit_group;");
            asm volatile("cp.async.wait_group 1;");
        } else {
            asm volatile("cp.async.wait_group 0;");
        }
        __syncthreads();                          // cur tile visible everywhere
        if (mat != curmat) {                      // matrix boundary: restage W
            stage_w(sW, jobs.W[mat], tid);
            load_bias(bb, jobs.b[mat], tid);
            curmat = mat;
            __syncthreads();
        }
        tile_compute(cur, sW, bb, jobs.Y[mat], tt, jobs.M, tid);
        __syncthreads();                          // done with cur before reuse
        p ^= 1;
    }
}

// ---------------- CSR build --------------------------------------------------
extern "C" __global__ void hist_kernel(const int* __restrict__ s_idx, int E) {
    int e = blockIdx.x * blockDim.x + threadIdx.x;
    if (e == 0) g_total = 0;
    if (e < E) atomicAdd(&g_deg[s_idx[e]], 1);
}

extern "C" __global__ void __launch_bounds__(1024) alloc_kernel(int n) {
    __shared__ int wsum[32];
    __shared__ int sbase;
    const int tid = threadIdx.x, lane = tid & 31, wid = tid >> 5;
    int i = blockIdx.x * 1024 + tid;
    int v = (i < n) ? g_deg[i] : 0;
    int x = v;
    #pragma unroll
    for (int o = 1; o < 32; o <<= 1) {
        int y = __shfl_up_sync(0xffffffffu, x, o);
        if (lane >= o) x += y;
    }
    if (lane == 31) wsum[wid] = x;
    __syncthreads();
    if (wid == 0) {
        int s = wsum[lane];
        #pragma unroll
        for (int o = 1; o < 32; o <<= 1) {
            int y = __shfl_up_sync(0xffffffffu, s, o);
            if (lane >= o) s += y;
        }
        wsum[lane] = s;
    }
    __syncthreads();
    if (tid == 0) sbase = atomicAdd(&g_total, wsum[31]);
    __syncthreads();
    int excl = x - v + (wid > 0 ? wsum[wid - 1] : 0);
    if (i < n) {
        int off = sbase + excl;
        g_rowptr[i] = off;
        g_cursor[i] = off;
    }
}

extern "C" __global__ void scatter_kernel(const int* __restrict__ s_idx,
                                          const int* __restrict__ d_idx, int E) {
    int e = blockIdx.x * blockDim.x + threadIdx.x;
    if (e < E) {
        int pos = atomicAdd(&g_cursor[s_idx[e]], 1);
        g_perm[pos] = d_idx[e];
    }
}

// ---------------- per-node attention (warp per node, CSR, unroll-8) ----------
extern "C" __global__ void __launch_bounds__(256) node_attn_kernel(int n_nodes) {
    int node = (int)((blockIdx.x * 256u + threadIdx.x) >> 5);
    if (node >= n_nodes) return;
    const int lane = threadIdx.x & 31;   // 4 lanes per head (16 floats)

    const int beg = g_rowptr[node];
    const int end = beg + g_deg[node];

    const float4 q4 = __ldcs((const float4*)(g_Q + (size_t)node * HID) + lane);
    float4 acc = make_float4(0.f, 0.f, 0.f, 0.f);
    float z = 0.f;

    for (int i = beg; i < end; i += 8) {
        int dd[8];
        dd[0] = __ldg(g_perm + i);
        #pragma unroll
        for (int j = 1; j < 8; j++)
            dd[j] = (i + j < end) ? __ldg(g_perm + i + j) : dd[0];

        float4 kk[8], vv[8];
        #pragma unroll
        for (int j = 0; j < 8; j++) {
            kk[j] = __ldg((const float4*)(g_K + (size_t)dd[j] * HID) + lane);
            vv[j] = __ldg((const float4*)(g_V + (size_t)dd[j] * HID) + lane);
        }

        float s[8];
        #pragma unroll
        for (int j = 0; j < 8; j++)
            s[j] = q4.x * kk[j].x + q4.y * kk[j].y + q4.z * kk[j].z + q4.w * kk[j].w;
        #pragma unroll
        for (int j = 0; j < 8; j++)
            s[j] += __shfl_xor_sync(0xffffffffu, s[j], 1);
        #pragma unroll
        for (int j = 0; j < 8; j++)
            s[j] += __shfl_xor_sync(0xffffffffu, s[j], 2);

        #pragma unroll
        for (int j = 0; j < 8; j++) {
            float p = (j == 0 || i + j < end) ? __expf(s[j] * 0.25f) : 0.f;
            z += p;
            acc.x += p * vv[j].x;
            acc.y += p * vv[j].y;
            acc.z += p * vv[j].z;
            acc.w += p * vv[j].w;
        }
    }

    float inv = (z > 0.f) ? (1.f / z) : 0.f;
    __stcs((float4*)(g_AGG + (size_t)node * HID) + lane,
           make_float4(acc.x * inv, acc.y * inv, acc.z * inv, acc.w * inv));
}

// ---------------- launch -----------------------------------------------------
extern "C" void kernel_launch(void* const* d_in, const int* in_sizes, int n_in,
                              void* d_out, int out_size) {
    const float* src_x = (const float*)d_in[0];
    const float* dst_x = (const float*)d_in[1];
    const float* Wq = (const float*)d_in[2];
    const float* bq = (const float*)d_in[3];
    const float* Wk = (const float*)d_in[4];
    const float* bk = (const float*)d_in[5];
    const float* Wv = (const float*)d_in[6];
    const float* bv = (const float*)d_in[7];
    const float* Wo = (const float*)d_in[8];
    const float* bo = (const float*)d_in[9];
    const int* ei = (const int*)d_in[10];

    const int N = in_sizes[0] / HID;
    const int E = in_sizes[10] / 2;
    const int* s_idx = ei;
    const int* d_idx = ei + E;

    float *Qp, *Kp, *Vp, *Ap;
    cudaGetSymbolAddress((void**)&Qp, g_Q);
    cudaGetSymbolAddress((void**)&Kp, g_K);
    cudaGetSymbolAddress((void**)&Vp, g_V);
    cudaGetSymbolAddress((void**)&Ap, g_AGG);
    void* degp;
    cudaGetSymbolAddress(&degp, g_deg);

    int sm_count = 148;
    cudaDeviceGetAttribute(&sm_count, cudaDevAttrMultiProcessorCount, 0);

    cudaFuncSetAttribute(gemm_multi, cudaFuncAttributeMaxDynamicSharedMemorySize, GEMM_SMEM);

    // CSR build
    cudaMemsetAsync(degp, 0, (size_t)N * sizeof(int));
    hist_kernel<<<(E + 255) / 256, 256>>>(s_idx, E);
    alloc_kernel<<<(N + 1023) / 1024, 1024>>>(N);
    scatter_kernel<<<(E + 255) / 256, 256>>>(s_idx, d_idx, E);

    // K, V, Q projections in one persistent launch
    Jobs3 qkv;
    qkv.X[0] = dst_x; qkv.W[0] = Wk; qkv.b[0] = bk; qkv.Y[0] = Kp;
    qkv.X[1] = dst_x; qkv.W[1] = Wv; qkv.b[1] = bv; qkv.Y[1] = Vp;
    qkv.X[2] = src_x; qkv.W[2] = Wq; qkv.b[2] = bq; qkv.Y[2] = Qp;
    qkv.nmats = 3; qkv.M = N;
    gemm_multi<<<sm_count, GTH, GEMM_SMEM>>>(qkv);

    // fused score/softmax/aggregate
    node_attn_kernel<<<(N + 7) / 8, 256>>>(N);

    // output projection
    Jobs3 oj;
    oj.X[0] = Ap; oj.W[0] = Wo; oj.b[0] = bo; oj.Y[0] = (float*)d_out;
    oj.X[1] = nullptr; oj.W[1] = nullptr; oj.b[1] = nullptr; oj.Y[1] = nullptr;
    oj.X[2] = nullptr; oj.W[2] = nullptr; oj.b[2] = nullptr; oj.Y[2] = nullptr;
    oj.nmats = 1; oj.M = N;
    gemm_multi<<<sm_count, GTH, GEMM_SMEM>>>(oj);
}

// round 10
// speedup vs baseline: 1.4537x; 1.4537x over previous
#include <cuda_runtime.h>
#include <cstdint>

#define NNODES 100000
#define NEDGES 640000
#define HID    128

// ---------------- scratch (device globals) ----------------------------------
__device__ float g_Q[(size_t)NNODES * HID];
__device__ float g_K[(size_t)NNODES * HID];
__device__ float g_V[(size_t)NNODES * HID];
__device__ float g_AGG[(size_t)NNODES * HID];
__device__ int   g_deg[NNODES];
__device__ int   g_rowptr[NNODES];
__device__ int   g_cursor[NNODES];
__device__ int   g_perm[NEDGES];     // destination node ids, CSR-grouped
__device__ int   g_total;

// ---------------- helpers ----------------------------------------------------
__device__ __forceinline__ uint32_t f2tf32(float x) {
    uint32_t r;
    asm("cvt.rna.tf32.f32 %0, %1;" : "=r"(r) : "f"(x));
    return r;
}

__device__ __forceinline__ void mma_tf32(float& c0, float& c1, float& c2, float& c3,
                                         uint32_t a0, uint32_t a1, uint32_t a2, uint32_t a3,
                                         uint32_t b0, uint32_t b1) {
    asm volatile(
        "mma.sync.aligned.m16n8k8.row.col.f32.tf32.tf32.f32 "
        "{%0,%1,%2,%3}, {%4,%5,%6,%7}, {%8,%9}, {%0,%1,%2,%3};"
        : "+f"(c0), "+f"(c1), "+f"(c2), "+f"(c3)
        : "r"(a0), "r"(a1), "r"(a2), "r"(a3), "r"(b0), "r"(b1));
}

// ---------------- persistent GEMM with cp.async double buffering ------------
// Y[M,128] = X[M,128] @ W^T + b.
// W staged once, tf32(RNA)-converted, pair-interleaved
// (pos(k)=(k&~7)|((k&3)<<1)|((k>>2)&1)) so a (k,k+4) B pair is one LDS.64.
// X tiles stream RAW fp32 via cp.async.cg into a double buffer (stride 132
// words -> conflict-free LDS.32 A-fragments). A feeds the mma as raw fp32
// bits (tf32 truncation) — no cvt in the critical LDS->mma chain.
// (Truncated-A numerics validated: rel_err 6.0e-4 < 1e-3.)
#define SLDW 136
#define SXW  132
#define TROWS 128   // rows per X tile; warp = 32 rows x 64 cols
#define GEMM_SMEM ((128 * SLDW + 2 * TROWS * SXW) * 4)

__device__ __forceinline__ void stage_w(uint32_t* sW, const float* __restrict__ W, int tid) {
    #pragma unroll
    for (int j = 0; j < 16; j++) {
        int f = j * 256 + tid;
        int r = f >> 5, c4 = f & 31, c = c4 * 4;
        float4 w4 = *(const float4*)(W + r * HID + c);
        int base = r * SLDW + (c & ~7) + (c4 & 1);
        sW[base + 0] = f2tf32(w4.x);
        sW[base + 2] = f2tf32(w4.y);
        sW[base + 4] = f2tf32(w4.z);
        sW[base + 6] = f2tf32(w4.w);
    }
}

__device__ __forceinline__ void cp_async_tile(float* sX, const float* __restrict__ X,
                                              int tile, int M, int tid) {
    uint32_t sbase = (uint32_t)__cvta_generic_to_shared(sX);
    int rbase = tile * TROWS;
    #pragma unroll
    for (int j = 0; j < 16; j++) {
        int f = j * 256 + tid;
        int r = f >> 5, c4 = f & 31;
        int gr = rbase + r;
        if (gr < M) {
            uint32_t sa = sbase + (uint32_t)(r * SXW + c4 * 4) * 4u;
            asm volatile("cp.async.cg.shared.global [%0], [%1], 16;"
                         :: "r"(sa), "l"(X + (size_t)gr * HID + c4 * 4));
        }
        // OOB rows: stale smem harmless — those output rows are masked.
    }
}

__device__ __forceinline__ void tile_compute1(
    const float* __restrict__ sX, const uint32_t* __restrict__ sW,
    const float* __restrict__ b0, float* __restrict__ Y0,
    int tile, int M, int tid) {

    const int w = tid >> 5, lane = tid & 31;
    const int g = lane >> 2, tig = lane & 3;
    const int mg = w >> 1;              // 4 groups of 32 rows
    const int nbase = (w & 1) * 64;     // 2 column halves

    float c[2][8][4];
    #pragma unroll
    for (int s = 0; s < 2; s++)
        #pragma unroll
        for (int nt = 0; nt < 8; nt++)
            c[s][nt][0] = c[s][nt][1] = c[s][nt][2] = c[s][nt][3] = 0.f;

    const uint32_t* ax = (const uint32_t*)(sX + (mg * 32 + g) * SXW) + tig;

    #pragma unroll 4
    for (int kt = 0; kt < 16; kt++) {
        const int ko = kt * 8;
        // rows g, g+8, g+16, g+24 in the 32-row group; k = ko+tig, ko+tig+4
        // raw fp32 bits -> tf32 operand (truncation; no cvt on critical path)
        uint32_t a0  = ax[ko];
        uint32_t a0b = ax[ko + 4];
        uint32_t a1  = ax[ko + 8 * SXW];
        uint32_t a1b = ax[ko + 8 * SXW + 4];
        uint32_t a2  = ax[ko + 16 * SXW];
        uint32_t a2b = ax[ko + 16 * SXW + 4];
        uint32_t a3  = ax[ko + 24 * SXW];
        uint32_t a3b = ax[ko + 24 * SXW + 4];
        #pragma unroll
        for (int nt = 0; nt < 8; nt++) {
            const uint32_t* bw = sW + (nbase + nt * 8 + g) * SLDW + ko + tig * 2;
            uint2 b = *(const uint2*)bw;
            mma_tf32(c[0][nt][0], c[0][nt][1], c[0][nt][2], c[0][nt][3],
                     a0, a1, a0b, a1b, b.x, b.y);
            mma_tf32(c[1][nt][0], c[1][nt][1], c[1][nt][2], c[1][nt][3],
                     a2, a3, a2b, a3b, b.x, b.y);
        }
    }

    #pragma unroll
    for (int s = 0; s < 2; s++) {
        const int row0 = tile * TROWS + mg * 32 + s * 16 + g;
        const int row1 = row0 + 8;
        #pragma unroll
        for (int nt = 0; nt < 8; nt++) {
            int col = nbase + nt * 8 + tig * 2;
            float bb0 = __ldg(b0 + col), bb1 = __ldg(b0 + col + 1);
            if (row0 < M) *(float2*)(Y0 + (size_t)row0 * HID + col) =
                make_float2(c[s][nt][0] + bb0, c[s][nt][1] + bb1);
            if (row1 < M) *(float2*)(Y0 + (size_t)row1 * HID + col) =
                make_float2(c[s][nt][2] + bb0, c[s][nt][3] + bb1);
        }
    }
}

extern "C" __global__ void __launch_bounds__(256, 1)
gemm_p1(const float* __restrict__ X, const float* __restrict__ W0,
        const float* __restrict__ b0, float* __restrict__ Y0, int M) {
    extern __shared__ uint32_t smem[];
    uint32_t* sW = smem;
    float* sXa = (float*)(smem + 128 * SLDW);
    float* sXb = sXa + TROWS * SXW;

    const int tid = threadIdx.x;
    const int ntiles = (M + TROWS - 1) / TROWS;

    stage_w(sW, W0, tid);

    int t = blockIdx.x;
    if (t >= ntiles) return;

    cp_async_tile(sXa, X, t, M, tid);
    asm volatile("cp.async.commit_group;");

    int p = 0;
    for (; t < ntiles; t += gridDim.x) {
        int tn = t + gridDim.x;
        float* cur = p ? sXb : sXa;
        float* nxt = p ? sXa : sXb;
        if (tn < ntiles) {
            cp_async_tile(nxt, X, tn, M, tid);   // overlaps with compute below
            asm volatile("cp.async.commit_group;");
            asm volatile("cp.async.wait_group 1;");
        } else {
            asm volatile("cp.async.wait_group 0;");
        }
        __syncthreads();                          // cur ready for all threads
        tile_compute1(cur, sW, b0, Y0, t, M, tid);
        __syncthreads();                          // done reading cur before overwrite
        p ^= 1;
    }
}

// ---------------- CSR build --------------------------------------------------
extern "C" __global__ void hist_kernel(const int* __restrict__ s_idx, int E) {
    int e = blockIdx.x * blockDim.x + threadIdx.x;
    if (e == 0) g_total = 0;
    if (e < E) atomicAdd(&g_deg[s_idx[e]], 1);
}

extern "C" __global__ void __launch_bounds__(1024) alloc_kernel(int n) {
    __shared__ int wsum[32];
    __shared__ int sbase;
    const int tid = threadIdx.x, lane = tid & 31, wid = tid >> 5;
    int i = blockIdx.x * 1024 + tid;
    int v = (i < n) ? g_deg[i] : 0;
    int x = v;
    #pragma unroll
    for (int o = 1; o < 32; o <<= 1) {
        int y = __shfl_up_sync(0xffffffffu, x, o);
        if (lane >= o) x += y;
    }
    if (lane == 31) wsum[wid] = x;
    __syncthreads();
    if (wid == 0) {
        int s = wsum[lane];
        #pragma unroll
        for (int o = 1; o < 32; o <<= 1) {
            int y = __shfl_up_sync(0xffffffffu, s, o);
            if (lane >= o) s += y;
        }
        wsum[lane] = s;
    }
    __syncthreads();
    if (tid == 0) sbase = atomicAdd(&g_total, wsum[31]);
    __syncthreads();
    int excl = x - v + (wid > 0 ? wsum[wid - 1] : 0);
    if (i < n) {
        int off = sbase + excl;
        g_rowptr[i] = off;
        g_cursor[i] = off;
    }
}

extern "C" __global__ void scatter_kernel(const int* __restrict__ s_idx,
                                          const int* __restrict__ d_idx, int E) {
    int e = blockIdx.x * blockDim.x + threadIdx.x;
    if (e < E) {
        int pos = atomicAdd(&g_cursor[s_idx[e]], 1);
        g_perm[pos] = d_idx[e];
    }
}

// ---------------- per-node attention (warp per node, CSR, unroll-4) ----------
extern "C" __global__ void __launch_bounds__(256) node_attn_kernel(int n_nodes) {
    int node = (int)((blockIdx.x * 256u + threadIdx.x) >> 5);
    if (node >= n_nodes) return;
    const int lane = threadIdx.x & 31;   // 4 lanes per head (16 floats)

    const int beg = g_rowptr[node];
    const int end = beg + g_deg[node];

    const float4 q4 = __ldcs((const float4*)(g_Q + (size_t)node * HID) + lane);
    float4 acc = make_float4(0.f, 0.f, 0.f, 0.f);
    float z = 0.f;

    for (int i = beg; i < end; i += 4) {
        const int rem = end - i;
        int d0 = __ldg(g_perm + i);
        int d1 = (rem > 1) ? __ldg(g_perm + i + 1) : d0;
        int d2 = (rem > 2) ? __ldg(g_perm + i + 2) : d0;
        int d3 = (rem > 3) ? __ldg(g_perm + i + 3) : d0;

        float4 k0 = __ldg((const float4*)(g_K + (size_t)d0 * HID) + lane);
        float4 v0 = __ldg((const float4*)(g_V + (size_t)d0 * HID) + lane);
        float4 k1 = __ldg((const float4*)(g_K + (size_t)d1 * HID) + lane);
        float4 v1 = __ldg((const float4*)(g_V + (size_t)d1 * HID) + lane);
        float4 k2 = __ldg((const float4*)(g_K + (size_t)d2 * HID) + lane);
        float4 v2 = __ldg((const float4*)(g_V + (size_t)d2 * HID) + lane);
        float4 k3 = __ldg((const float4*)(g_K + (size_t)d3 * HID) + lane);
        float4 v3 = __ldg((const float4*)(g_V + (size_t)d3 * HID) + lane);

        float s0 = q4.x * k0.x + q4.y * k0.y + q4.z * k0.z + q4.w * k0.w;
        float s1 = q4.x * k1.x + q4.y * k1.y + q4.z * k1.z + q4.w * k1.w;
        float s2 = q4.x * k2.x + q4.y * k2.y + q4.z * k2.z + q4.w * k2.w;
        float s3 = q4.x * k3.x + q4.y * k3.y + q4.z * k3.z + q4.w * k3.w;
        s0 += __shfl_xor_sync(0xffffffffu, s0, 1);
        s1 += __shfl_xor_sync(0xffffffffu, s1, 1);
        s2 += __shfl_xor_sync(0xffffffffu, s2, 1);
        s3 += __shfl_xor_sync(0xffffffffu, s3, 1);
        s0 += __shfl_xor_sync(0xffffffffu, s0, 2);
        s1 += __shfl_xor_sync(0xffffffffu, s1, 2);
        s2 += __shfl_xor_sync(0xffffffffu, s2, 2);
        s3 += __shfl_xor_sync(0xffffffffu, s3, 2);

        float p0 = __expf(s0 * 0.25f);                       // 1/sqrt(16)
        float p1 = (rem > 1) ? __expf(s1 * 0.25f) : 0.f;
        float p2 = (rem > 2) ? __expf(s2 * 0.25f) : 0.f;
        float p3 = (rem > 3) ? __expf(s3 * 0.25f) : 0.f;

        z += (p0 + p1) + (p2 + p3);
        acc.x += p0 * v0.x + p1 * v1.x + p2 * v2.x + p3 * v3.x;
        acc.y += p0 * v0.y + p1 * v1.y + p2 * v2.y + p3 * v3.y;
        acc.z += p0 * v0.z + p1 * v1.z + p2 * v2.z + p3 * v3.z;
        acc.w += p0 * v0.w + p1 * v1.w + p2 * v2.w + p3 * v3.w;
    }

    float inv = (z > 0.f) ? (1.f / z) : 0.f;
    __stcs((float4*)(g_AGG + (size_t)node * HID) + lane,
           make_float4(acc.x * inv, acc.y * inv, acc.z * inv, acc.w * inv));
}

// ---------------- launch -----------------------------------------------------
extern "C" void kernel_launch(void* const* d_in, const int* in_sizes, int n_in,
                              void* d_out, int out_size) {
    const float* src_x = (const float*)d_in[0];
    const float* dst_x = (const float*)d_in[1];
    const float* Wq = (const float*)d_in[2];
    const float* bq = (const float*)d_in[3];
    const float* Wk = (const float*)d_in[4];
    const float* bk = (const float*)d_in[5];
    const float* Wv = (const float*)d_in[6];
    const float* bv = (const float*)d_in[7];
    const float* Wo = (const float*)d_in[8];
    const float* bo = (const float*)d_in[9];
    const int* ei = (const int*)d_in[10];

    const int N = in_sizes[0] / HID;
    const int E = in_sizes[10] / 2;
    const int* s_idx = ei;
    const int* d_idx = ei + E;

    float *Qp, *Kp, *Vp, *Ap;
    cudaGetSymbolAddress((void**)&Qp, g_Q);
    cudaGetSymbolAddress((void**)&Kp, g_K);
    cudaGetSymbolAddress((void**)&Vp, g_V);
    cudaGetSymbolAddress((void**)&Ap, g_AGG);
    void* degp;
    cudaGetSymbolAddress(&degp, g_deg);

    int sm_count = 148;
    cudaDeviceGetAttribute(&sm_count, cudaDevAttrMultiProcessorCount, 0);

    cudaFuncSetAttribute(gemm_p1, cudaFuncAttributeMaxDynamicSharedMemorySize, GEMM_SMEM);

    // CSR build
    cudaMemsetAsync(degp, 0, (size_t)N * sizeof(int));
    hist_kernel<<<(E + 255) / 256, 256>>>(s_idx, E);
    alloc_kernel<<<(N + 1023) / 1024, 1024>>>(N);
    scatter_kernel<<<(E + 255) / 256, 256>>>(s_idx, d_idx, E);

    // Projections (cp.async double-buffered persistent GEMMs)
    gemm_p1<<<sm_count, 256, GEMM_SMEM>>>(dst_x, Wk, bk, Kp, N);
    gemm_p1<<<sm_count, 256, GEMM_SMEM>>>(dst_x, Wv, bv, Vp, N);
    gemm_p1<<<sm_count, 256, GEMM_SMEM>>>(src_x, Wq, bq, Qp, N);

    // fused score/softmax/aggregate
    node_attn_kernel<<<(N + 7) / 8, 256>>>(N);

    // output projection
    gemm_p1<<<sm_count, 256, GEMM_SMEM>>>(Ap, Wo, bo, (float*)d_out, N);
}

// round 11
// speedup vs baseline: 1.4575x; 1.0026x over previous
#include <cuda_runtime.h>
#include <cstdint>

#define NNODES 100000
#define NEDGES 640000
#define HID    128

// ---------------- scratch (device globals) ----------------------------------
__device__ float g_Q[(size_t)NNODES * HID];
__device__ float g_K[(size_t)NNODES * HID];
__device__ float g_V[(size_t)NNODES * HID];
__device__ float g_AGG[(size_t)NNODES * HID];
__device__ int   g_deg[NNODES];
__device__ int   g_rowptr[NNODES];
__device__ int   g_cursor[NNODES];
__device__ int   g_perm[NEDGES];     // destination node ids, CSR-grouped
__device__ int   g_total;

// ---------------- helpers ----------------------------------------------------
__device__ __forceinline__ uint32_t f2tf32(float x) {
    uint32_t r;
    asm("cvt.rna.tf32.f32 %0, %1;" : "=r"(r) : "f"(x));
    return r;
}

__device__ __forceinline__ void mma_tf32(float& c0, float& c1, float& c2, float& c3,
                                         uint32_t a0, uint32_t a1, uint32_t a2, uint32_t a3,
                                         uint32_t b0, uint32_t b1) {
    asm volatile(
        "mma.sync.aligned.m16n8k8.row.col.f32.tf32.tf32.f32 "
        "{%0,%1,%2,%3}, {%4,%5,%6,%7}, {%8,%9}, {%0,%1,%2,%3};"
        : "+f"(c0), "+f"(c1), "+f"(c2), "+f"(c3)
        : "r"(a0), "r"(a1), "r"(a2), "r"(a3), "r"(b0), "r"(b1));
}

// ---------------- persistent GEMM, 2 CTAs/SM ---------------------------------
// Y[M,128] = X[M,128] @ W^T + b.
// W staged once per CTA, tf32(RNA), pair-interleaved
// (pos(k)=(k&~7)|((k&3)<<1)|((k>>2)&1)) so a (k,k+4) B pair is one LDS.64.
// X tile (64 rows) streams raw fp32 via cp.async.cg into a SINGLE buffer; the
// staging latency of one CTA is hidden by the other CTA on the same SM
// (independent barrier domains). A feeds mma as raw fp32 bits (tf32
// truncation — validated rel_err 6.0e-4 < 1e-3).
// Warp tile = 32 rows x 32 cols (8 warps cover 64x128).
#define SLDW 136
#define SXW  132
#define TROWS 64
#define GEMM_SMEM ((128 * SLDW + TROWS * SXW) * 4)

__device__ __forceinline__ void stage_w(uint32_t* sW, const float* __restrict__ W, int tid) {
    #pragma unroll
    for (int j = 0; j < 16; j++) {
        int f = j * 256 + tid;
        int r = f >> 5, c4 = f & 31, c = c4 * 4;
        float4 w4 = *(const float4*)(W + r * HID + c);
        int base = r * SLDW + (c & ~7) + (c4 & 1);
        sW[base + 0] = f2tf32(w4.x);
        sW[base + 2] = f2tf32(w4.y);
        sW[base + 4] = f2tf32(w4.z);
        sW[base + 6] = f2tf32(w4.w);
    }
}

__device__ __forceinline__ void cp_async_tile(float* sX, const float* __restrict__ X,
                                              int tile, int M, int tid) {
    uint32_t sbase = (uint32_t)__cvta_generic_to_shared(sX);
    int rbase = tile * TROWS;
    #pragma unroll
    for (int j = 0; j < 8; j++) {
        int f = j * 256 + tid;
        int r = f >> 5, c4 = f & 31;
        int gr = rbase + r;
        if (gr < M) {
            uint32_t sa = sbase + (uint32_t)(r * SXW + c4 * 4) * 4u;
            asm volatile("cp.async.cg.shared.global [%0], [%1], 16;"
                         :: "r"(sa), "l"(X + (size_t)gr * HID + c4 * 4));
        }
        // OOB rows: stale smem harmless — those output rows are masked.
    }
}

__device__ __forceinline__ void tile_compute(
    const float* __restrict__ sX, const uint32_t* __restrict__ sW,
    const float* __restrict__ b0, float* __restrict__ Y0,
    int tile, int M, int tid) {

    const int w = tid >> 5, lane = tid & 31;
    const int g = lane >> 2, tig = lane & 3;
    const int mg = w >> 2;              // 2 groups of 32 rows
    const int nbase = (w & 3) * 32;     // 4 column quarters

    float c[2][4][4];
    #pragma unroll
    for (int s = 0; s < 2; s++)
        #pragma unroll
        for (int nt = 0; nt < 4; nt++)
            c[s][nt][0] = c[s][nt][1] = c[s][nt][2] = c[s][nt][3] = 0.f;

    const uint32_t* ax = (const uint32_t*)(sX + (mg * 32 + g) * SXW) + tig;

    #pragma unroll 4
    for (int kt = 0; kt < 16; kt++) {
        const int ko = kt * 8;
        // rows g, g+8, g+16, g+24 in the 32-row group; k = ko+tig, ko+tig+4
        uint32_t a0  = ax[ko];
        uint32_t a0b = ax[ko + 4];
        uint32_t a1  = ax[ko + 8 * SXW];
        uint32_t a1b = ax[ko + 8 * SXW + 4];
        uint32_t a2  = ax[ko + 16 * SXW];
        uint32_t a2b = ax[ko + 16 * SXW + 4];
        uint32_t a3  = ax[ko + 24 * SXW];
        uint32_t a3b = ax[ko + 24 * SXW + 4];
        #pragma unroll
        for (int nt = 0; nt < 4; nt++) {
            const uint32_t* bw = sW + (nbase + nt * 8 + g) * SLDW + ko + tig * 2;
            uint2 b = *(const uint2*)bw;
            mma_tf32(c[0][nt][0], c[0][nt][1], c[0][nt][2], c[0][nt][3],
                     a0, a1, a0b, a1b, b.x, b.y);
            mma_tf32(c[1][nt][0], c[1][nt][1], c[1][nt][2], c[1][nt][3],
                     a2, a3, a2b, a3b, b.x, b.y);
        }
    }

    #pragma unroll
    for (int s = 0; s < 2; s++) {
        const int row0 = tile * TROWS + mg * 32 + s * 16 + g;
        const int row1 = row0 + 8;
        #pragma unroll
        for (int nt = 0; nt < 4; nt++) {
            int col = nbase + nt * 8 + tig * 2;
            float bb0 = __ldg(b0 + col), bb1 = __ldg(b0 + col + 1);
            if (row0 < M) *(float2*)(Y0 + (size_t)row0 * HID + col) =
                make_float2(c[s][nt][0] + bb0, c[s][nt][1] + bb1);
            if (row1 < M) *(float2*)(Y0 + (size_t)row1 * HID + col) =
                make_float2(c[s][nt][2] + bb0, c[s][nt][3] + bb1);
        }
    }
}

extern "C" __global__ void __launch_bounds__(256, 2)
gemm_p1(const float* __restrict__ X, const float* __restrict__ W0,
        const float* __restrict__ b0, float* __restrict__ Y0, int M) {
    extern __shared__ uint32_t smem[];
    uint32_t* sW = smem;
    float* sX = (float*)(smem + 128 * SLDW);

    const int tid = threadIdx.x;
    const int ntiles = (M + TROWS - 1) / TROWS;

    stage_w(sW, W0, tid);

    for (int t = blockIdx.x; t < ntiles; t += gridDim.x) {
        cp_async_tile(sX, X, t, M, tid);
        asm volatile("cp.async.commit_group;");
        asm volatile("cp.async.wait_group 0;");
        __syncthreads();                         // tile visible to all warps
        tile_compute(sX, sW, b0, Y0, t, M, tid);
        __syncthreads();                         // done reading before overwrite
    }
}

// ---------------- CSR build --------------------------------------------------
extern "C" __global__ void hist_kernel(const int* __restrict__ s_idx, int E) {
    int e = blockIdx.x * blockDim.x + threadIdx.x;
    if (e == 0) g_total = 0;
    if (e < E) atomicAdd(&g_deg[s_idx[e]], 1);
}

extern "C" __global__ void __launch_bounds__(1024) alloc_kernel(int n) {
    __shared__ int wsum[32];
    __shared__ int sbase;
    const int tid = threadIdx.x, lane = tid & 31, wid = tid >> 5;
    int i = blockIdx.x * 1024 + tid;
    int v = (i < n) ? g_deg[i] : 0;
    int x = v;
    #pragma unroll
    for (int o = 1; o < 32; o <<= 1) {
        int y = __shfl_up_sync(0xffffffffu, x, o);
        if (lane >= o) x += y;
    }
    if (lane == 31) wsum[wid] = x;
    __syncthreads();
    if (wid == 0) {
        int s = wsum[lane];
        #pragma unroll
        for (int o = 1; o < 32; o <<= 1) {
            int y = __shfl_up_sync(0xffffffffu, s, o);
            if (lane >= o) s += y;
        }
        wsum[lane] = s;
    }
    __syncthreads();
    if (tid == 0) sbase = atomicAdd(&g_total, wsum[31]);
    __syncthreads();
    int excl = x - v + (wid > 0 ? wsum[wid - 1] : 0);
    if (i < n) {
        int off = sbase + excl;
        g_rowptr[i] = off;
        g_cursor[i] = off;
    }
}

extern "C" __global__ void scatter_kernel(const int* __restrict__ s_idx,
                                          const int* __restrict__ d_idx, int E) {
    int e = blockIdx.x * blockDim.x + threadIdx.x;
    if (e < E) {
        int pos = atomicAdd(&g_cursor[s_idx[e]], 1);
        g_perm[pos] = d_idx[e];
    }
}

// ---------------- per-node attention (warp per node, CSR, unroll-4) ----------
extern "C" __global__ void __launch_bounds__(256) node_attn_kernel(int n_nodes) {
    int node = (int)((blockIdx.x * 256u + threadIdx.x) >> 5);
    if (node >= n_nodes) return;
    const int lane = threadIdx.x & 31;   // 4 lanes per head (16 floats)

    const int beg = g_rowptr[node];
    const int end = beg + g_deg[node];

    const float4 q4 = __ldcs((const float4*)(g_Q + (size_t)node * HID) + lane);
    float4 acc = make_float4(0.f, 0.f, 0.f, 0.f);
    float z = 0.f;

    for (int i = beg; i < end; i += 4) {
        const int rem = end - i;
        int d0 = __ldg(g_perm + i);
        int d1 = (rem > 1) ? __ldg(g_perm + i + 1) : d0;
        int d2 = (rem > 2) ? __ldg(g_perm + i + 2) : d0;
        int d3 = (rem > 3) ? __ldg(g_perm + i + 3) : d0;

        float4 k0 = __ldg((const float4*)(g_K + (size_t)d0 * HID) + lane);
        float4 v0 = __ldg((const float4*)(g_V + (size_t)d0 * HID) + lane);
        float4 k1 = __ldg((const float4*)(g_K + (size_t)d1 * HID) + lane);
        float4 v1 = __ldg((const float4*)(g_V + (size_t)d1 * HID) + lane);
        float4 k2 = __ldg((const float4*)(g_K + (size_t)d2 * HID) + lane);
        float4 v2 = __ldg((const float4*)(g_V + (size_t)d2 * HID) + lane);
        float4 k3 = __ldg((const float4*)(g_K + (size_t)d3 * HID) + lane);
        float4 v3 = __ldg((const float4*)(g_V + (size_t)d3 * HID) + lane);

        float s0 = q4.x * k0.x + q4.y * k0.y + q4.z * k0.z + q4.w * k0.w;
        float s1 = q4.x * k1.x + q4.y * k1.y + q4.z * k1.z + q4.w * k1.w;
        float s2 = q4.x * k2.x + q4.y * k2.y + q4.z * k2.z + q4.w * k2.w;
        float s3 = q4.x * k3.x + q4.y * k3.y + q4.z * k3.z + q4.w * k3.w;
        s0 += __shfl_xor_sync(0xffffffffu, s0, 1);
        s1 += __shfl_xor_sync(0xffffffffu, s1, 1);
        s2 += __shfl_xor_sync(0xffffffffu, s2, 1);
        s3 += __shfl_xor_sync(0xffffffffu, s3, 1);
        s0 += __shfl_xor_sync(0xffffffffu, s0, 2);
        s1 += __shfl_xor_sync(0xffffffffu, s1, 2);
        s2 += __shfl_xor_sync(0xffffffffu, s2, 2);
        s3 += __shfl_xor_sync(0xffffffffu, s3, 2);

        float p0 = __expf(s0 * 0.25f);                       // 1/sqrt(16)
        float p1 = (rem > 1) ? __expf(s1 * 0.25f) : 0.f;
        float p2 = (rem > 2) ? __expf(s2 * 0.25f) : 0.f;
        float p3 = (rem > 3) ? __expf(s3 * 0.25f) : 0.f;

        z += (p0 + p1) + (p2 + p3);
        acc.x += p0 * v0.x + p1 * v1.x + p2 * v2.x + p3 * v3.x;
        acc.y += p0 * v0.y + p1 * v1.y + p2 * v2.y + p3 * v3.y;
        acc.z += p0 * v0.z + p1 * v1.z + p2 * v2.z + p3 * v3.z;
        acc.w += p0 * v0.w + p1 * v1.w + p2 * v2.w + p3 * v3.w;
    }

    float inv = (z > 0.f) ? (1.f / z) : 0.f;
    __stcs((float4*)(g_AGG + (size_t)node * HID) + lane,
           make_float4(acc.x * inv, acc.y * inv, acc.z * inv, acc.w * inv));
}

// ---------------- launch -----------------------------------------------------
extern "C" void kernel_launch(void* const* d_in, const int* in_sizes, int n_in,
                              void* d_out, int out_size) {
    const float* src_x = (const float*)d_in[0];
    const float* dst_x = (const float*)d_in[1];
    const float* Wq = (const float*)d_in[2];
    const float* bq = (const float*)d_in[3];
    const float* Wk = (const float*)d_in[4];
    const float* bk = (const float*)d_in[5];
    const float* Wv = (const float*)d_in[6];
    const float* bv = (const float*)d_in[7];
    const float* Wo = (const float*)d_in[8];
    const float* bo = (const float*)d_in[9];
    const int* ei = (const int*)d_in[10];

    const int N = in_sizes[0] / HID;
    const int E = in_sizes[10] / 2;
    const int* s_idx = ei;
    const int* d_idx = ei + E;

    float *Qp, *Kp, *Vp, *Ap;
    cudaGetSymbolAddress((void**)&Qp, g_Q);
    cudaGetSymbolAddress((void**)&Kp, g_K);
    cudaGetSymbolAddress((void**)&Vp, g_V);
    cudaGetSymbolAddress((void**)&Ap, g_AGG);
    void* degp;
    cudaGetSymbolAddress(&degp, g_deg);

    int sm_count = 148;
    cudaDeviceGetAttribute(&sm_count, cudaDevAttrMultiProcessorCount, 0);

    cudaFuncSetAttribute(gemm_p1, cudaFuncAttributeMaxDynamicSharedMemorySize, GEMM_SMEM);

    // CSR build
    cudaMemsetAsync(degp, 0, (size_t)N * sizeof(int));
    hist_kernel<<<(E + 255) / 256, 256>>>(s_idx, E);
    alloc_kernel<<<(N + 1023) / 1024, 1024>>>(N);
    scatter_kernel<<<(E + 255) / 256, 256>>>(s_idx, d_idx, E);

    // Projections: 2 CTAs per SM, cross-CTA staging/compute overlap
    const int ggrid = 2 * sm_count;
    gemm_p1<<<ggrid, 256, GEMM_SMEM>>>(dst_x, Wk, bk, Kp, N);
    gemm_p1<<<ggrid, 256, GEMM_SMEM>>>(dst_x, Wv, bv, Vp, N);
    gemm_p1<<<ggrid, 256, GEMM_SMEM>>>(src_x, Wq, bq, Qp, N);

    // fused score/softmax/aggregate
    node_attn_kernel<<<(N + 7) / 8, 256>>>(N);

    // output projection
    gemm_p1<<<ggrid, 256, GEMM_SMEM>>>(Ap, Wo, bo, (float*)d_out, N);
}